// round 3
// baseline (speedup 1.0000x reference)
#include <cuda_runtime.h>
#include <cstdint>

// DenseGridNet: trilevel bilinear grid features + MLP 13->64->64->3.
// Scalar fp32 throughout (exact math). Register-resident activations,
// smem-broadcast weights. No u64/f32x2 packing (caused ptxas spill in R0/R1).

#define HID 64
#define EMB 13
#define THREADS 128
#define BLOCKS 4096

// Shared weight staging (~21.3 KB)
struct __align__(16) SmemW {
    float w1[EMB * HID];   // 13*64, row-major [in][out]
    float b1[HID];
    float w2[HID * HID];   // 64*64
    float b2[HID];
    float w3[HID * 4];     // 64x3 padded to 64x4 (col 3 = 0)
    float b3[4];
};

__device__ __forceinline__ float4 bilerp_level(const float4* __restrict__ tab,
                                               int res, float u, float v) {
    float sx = u * (float)res;
    float sy = v * (float)res;
    int x0 = (int)sx;            // truncation; matches astype(int32) for non-neg
    int y0 = (int)sy;
    float wx = sx - (float)x0;
    float wy = sy - (float)y0;
    int x1 = min(x0 + 1, res);
    int y1 = min(y0 + 1, res);
    // Reference indexes with row stride == res (not res+1). Replicate exactly.
    int r0 = y0 * res;
    int r1 = y1 * res;
    float4 v00 = tab[r0 + x0];
    float4 v10 = tab[r0 + x1];
    float4 v01 = tab[r1 + x0];
    float4 v11 = tab[r1 + x1];
    float omwx = 1.0f - wx;
    float omwy = 1.0f - wy;
    float4 o;
    float t, c;
    t = v00.x * omwx + v10.x * wx; c = v01.x * omwx + v11.x * wx; o.x = t * omwy + c * wy;
    t = v00.y * omwx + v10.y * wx; c = v01.y * omwx + v11.y * wx; o.y = t * omwy + c * wy;
    t = v00.z * omwx + v10.z * wx; c = v01.z * omwx + v11.z * wx; o.z = t * omwy + c * wy;
    t = v00.w * omwx + v10.w * wx; c = v01.w * omwx + v11.w * wx; o.w = t * omwy + c * wy;
    return o;
}

__global__ __launch_bounds__(THREADS)
void densegrid_kernel(const float* __restrict__ x,
                      const float4* __restrict__ emb0,
                      const float4* __restrict__ emb1,
                      const float4* __restrict__ emb2,
                      const float* __restrict__ w1, const float* __restrict__ b1,
                      const float* __restrict__ w2, const float* __restrict__ b2,
                      const float* __restrict__ w3, const float* __restrict__ b3,
                      float* __restrict__ out, int n) {
    __shared__ SmemW s;

    for (int t = threadIdx.x; t < EMB * HID; t += THREADS) s.w1[t] = w1[t];
    for (int t = threadIdx.x; t < HID; t += THREADS) s.b1[t] = b1[t];
    for (int t = threadIdx.x; t < HID * HID; t += THREADS) s.w2[t] = w2[t];
    for (int t = threadIdx.x; t < HID; t += THREADS) s.b2[t] = b2[t];
    for (int t = threadIdx.x; t < HID * 4; t += THREADS) {
        int r = t >> 2, c = t & 3;
        s.w3[t] = (c < 3) ? w3[r * 3 + c] : 0.0f;
    }
    if (threadIdx.x < 4) s.b3[threadIdx.x] = (threadIdx.x < 3) ? b3[threadIdx.x] : 0.0f;
    __syncthreads();

    const float4* w1v = (const float4*)s.w1;
    const float4* w2v = (const float4*)s.w2;
    const float4* w3v = (const float4*)s.w3;

    int stride = gridDim.x * THREADS;
    for (int idx = blockIdx.x * THREADS + threadIdx.x; idx < n; idx += stride) {
        float idf = x[idx * 3 + 0];
        float u   = x[idx * 3 + 1];
        float v   = x[idx * 3 + 2];

        float4 f0 = bilerp_level(emb0, 512, u, v);
        float4 f1 = bilerp_level(emb1, 264, u, v);
        float4 f2 = bilerp_level(emb2, 16,  u, v);
        float hin[EMB];
        hin[0] = idf;
        hin[1] = f0.x; hin[2]  = f0.y; hin[3]  = f0.z; hin[4]  = f0.w;
        hin[5] = f1.x; hin[6]  = f1.y; hin[7]  = f1.z; hin[8]  = f1.w;
        hin[9] = f2.x; hin[10] = f2.y; hin[11] = f2.z; hin[12] = f2.w;

        // ---- layer 1: 13 -> 64 + relu ----
        float acc[HID];
        #pragma unroll
        for (int j = 0; j < HID; j++) acc[j] = s.b1[j];
        #pragma unroll
        for (int i = 0; i < EMB; i++) {
            float hv = hin[i];
            #pragma unroll
            for (int q = 0; q < HID / 4; q++) {
                float4 w = w1v[i * (HID / 4) + q];
                acc[4 * q + 0] = fmaf(hv, w.x, acc[4 * q + 0]);
                acc[4 * q + 1] = fmaf(hv, w.y, acc[4 * q + 1]);
                acc[4 * q + 2] = fmaf(hv, w.z, acc[4 * q + 2]);
                acc[4 * q + 3] = fmaf(hv, w.w, acc[4 * q + 3]);
            }
        }
        float h[HID];
        #pragma unroll
        for (int j = 0; j < HID; j++) h[j] = fmaxf(acc[j], 0.0f);

        // ---- layer 2: 64 -> 64 + relu ----
        #pragma unroll
        for (int j = 0; j < HID; j++) acc[j] = s.b2[j];
        #pragma unroll
        for (int i = 0; i < HID; i++) {
            float hv = h[i];
            #pragma unroll
            for (int q = 0; q < HID / 4; q++) {
                float4 w = w2v[i * (HID / 4) + q];
                acc[4 * q + 0] = fmaf(hv, w.x, acc[4 * q + 0]);
                acc[4 * q + 1] = fmaf(hv, w.y, acc[4 * q + 1]);
                acc[4 * q + 2] = fmaf(hv, w.z, acc[4 * q + 2]);
                acc[4 * q + 3] = fmaf(hv, w.w, acc[4 * q + 3]);
            }
        }
        #pragma unroll
        for (int j = 0; j < HID; j++) h[j] = fmaxf(acc[j], 0.0f);

        // ---- layer 3: 64 -> 3 ----
        float o0 = s.b3[0], o1 = s.b3[1], o2 = s.b3[2];
        #pragma unroll
        for (int i = 0; i < HID; i++) {
            float4 w = w3v[i];
            float hv = h[i];
            o0 = fmaf(hv, w.x, o0);
            o1 = fmaf(hv, w.y, o1);
            o2 = fmaf(hv, w.z, o2);
        }

        out[idx * 3 + 0] = o0;
        out[idx * 3 + 1] = o1;
        out[idx * 3 + 2] = o2;
    }
}

extern "C" void kernel_launch(void* const* d_in, const int* in_sizes, int n_in,
                              void* d_out, int out_size) {
    const float* x    = (const float*)d_in[0];
    const float4* e0  = (const float4*)d_in[1];
    const float4* e1  = (const float4*)d_in[2];
    const float4* e2  = (const float4*)d_in[3];
    const float* w1   = (const float*)d_in[4];
    const float* b1   = (const float*)d_in[5];
    const float* w2   = (const float*)d_in[6];
    const float* b2   = (const float*)d_in[7];
    const float* w3   = (const float*)d_in[8];
    const float* b3   = (const float*)d_in[9];
    float* out        = (float*)d_out;
    int n = in_sizes[0] / 3;
    (void)n_in; (void)out_size;
    densegrid_kernel<<<BLOCKS, THREADS>>>(x, e0, e1, e2, w1, b1, w2, b2, w3, b3, out, n);
}

// round 4
// speedup vs baseline: 1.1436x; 1.1436x over previous
#include <cuda_runtime.h>
#include <cstdint>

// DenseGridNet: trilevel bilinear grid features + MLP 13->64->64->3.
// GEMM-style tiling: 64 points per CTA, activations staged in SMEM between
// layers, register tile = 4 outputs x 16 points per thread, point-pairs packed
// as fma.rn.f32x2 (exact fp32 math, 2x FFMA issue throughput on sm_100+).

#define HID 64
#define EMB 13
#define TILE 64
#define THREADS 64
#define RS 68   // activation row stride (floats): 16B-aligned rows, de-conflicted STS

typedef unsigned long long u64;

__device__ __forceinline__ u64 pack2(float a) {
    u64 r;
    asm("mov.b64 %0, {%1, %1};" : "=l"(r) : "f"(a));
    return r;
}
__device__ __forceinline__ u64 fma2(u64 a, u64 b, u64 c) {
    u64 d;
    asm("fma.rn.f32x2 %0, %1, %2, %3;" : "=l"(d) : "l"(a), "l"(b), "l"(c));
    return d;
}
__device__ __forceinline__ void unpack2(u64 p, float& lo, float& hi) {
    asm("mov.b64 {%0, %1}, %2;" : "=f"(lo), "=f"(hi) : "l"(p));
}

__device__ __forceinline__ float4 bilerp_level(const float4* __restrict__ tab,
                                               int res, float u, float v) {
    float sx = u * (float)res;
    float sy = v * (float)res;
    int x0 = (int)sx;            // truncation; matches astype(int32) for non-neg
    int y0 = (int)sy;
    float wx = sx - (float)x0;
    float wy = sy - (float)y0;
    int x1 = min(x0 + 1, res);
    int y1 = min(y0 + 1, res);
    // Reference indexes with row stride == res (not res+1). Replicate exactly.
    int r0 = y0 * res;
    int r1 = y1 * res;
    float4 v00 = tab[r0 + x0];
    float4 v10 = tab[r0 + x1];
    float4 v01 = tab[r1 + x0];
    float4 v11 = tab[r1 + x1];
    float omwx = 1.0f - wx;
    float omwy = 1.0f - wy;
    float4 o;
    float t, c;
    t = v00.x * omwx + v10.x * wx; c = v01.x * omwx + v11.x * wx; o.x = t * omwy + c * wy;
    t = v00.y * omwx + v10.y * wx; c = v01.y * omwx + v11.y * wx; o.y = t * omwy + c * wy;
    t = v00.z * omwx + v10.z * wx; c = v01.z * omwx + v11.z * wx; o.z = t * omwy + c * wy;
    t = v00.w * omwx + v10.w * wx; c = v01.w * omwx + v11.w * wx; o.w = t * omwy + c * wy;
    return o;
}

__global__ __launch_bounds__(THREADS)
void densegrid_kernel(const float* __restrict__ x,
                      const float4* __restrict__ emb0,
                      const float4* __restrict__ emb1,
                      const float4* __restrict__ emb2,
                      const float* __restrict__ w1, const float* __restrict__ b1,
                      const float* __restrict__ w2, const float* __restrict__ b2,
                      const float* __restrict__ w3, const float* __restrict__ b3,
                      float* __restrict__ out, int n) {
    __shared__ __align__(16) float w1s[EMB * HID];
    __shared__ __align__(16) float b1s[HID];
    __shared__ __align__(16) float w2s[HID * HID];
    __shared__ __align__(16) float b2s[HID];
    __shared__ __align__(16) float w3s[HID * 4];   // 64x3 padded to 64x4
    __shared__ __align__(16) float b3s[4];
    __shared__ __align__(16) float A0[EMB * RS];   // input features [13][pts]
    __shared__ __align__(16) float A1[HID * RS];   // activations    [64][pts]

    const int tid = threadIdx.x;

    // ---- cooperative weight staging ----
    for (int t = tid; t < EMB * HID; t += THREADS) w1s[t] = w1[t];
    for (int t = tid; t < HID; t += THREADS) b1s[t] = b1[t];
    for (int t = tid; t < HID * HID; t += THREADS) w2s[t] = w2[t];
    for (int t = tid; t < HID; t += THREADS) b2s[t] = b2[t];
    for (int t = tid; t < HID * 4; t += THREADS) {
        int r = t >> 2, c = t & 3;
        w3s[t] = (c < 3) ? w3[r * 3 + c] : 0.0f;
    }
    if (tid < 4) b3s[tid] = (tid < 3) ? b3[tid] : 0.0f;

    const int base = blockIdx.x * TILE;

    // ---- phase 0: features for this thread's point -> A0 ----
    {
        int idx = base + tid;
        if (idx >= n) idx = n - 1;   // safe clamp (N is a multiple of TILE anyway)
        float idf = x[idx * 3 + 0];
        float u   = x[idx * 3 + 1];
        float v   = x[idx * 3 + 2];
        float4 f0 = bilerp_level(emb0, 512, u, v);
        float4 f1 = bilerp_level(emb1, 264, u, v);
        float4 f2 = bilerp_level(emb2, 16,  u, v);
        A0[0 * RS + tid]  = idf;
        A0[1 * RS + tid]  = f0.x; A0[2 * RS + tid]  = f0.y;
        A0[3 * RS + tid]  = f0.z; A0[4 * RS + tid]  = f0.w;
        A0[5 * RS + tid]  = f1.x; A0[6 * RS + tid]  = f1.y;
        A0[7 * RS + tid]  = f1.z; A0[8 * RS + tid]  = f1.w;
        A0[9 * RS + tid]  = f2.x; A0[10 * RS + tid] = f2.y;
        A0[11 * RS + tid] = f2.z; A0[12 * RS + tid] = f2.w;
    }
    __syncthreads();

    const int to = tid & 15;   // output quad id: outs [4*to, 4*to+3]
    const int tp = tid >> 4;   // point group: pts [16*tp, 16*tp+15]

    // ---- phase 1: 13 -> 64 + relu, into A1 ----
    {
        u64 acc[4][8];
        #pragma unroll
        for (int o = 0; o < 4; o++) {
            u64 bb = pack2(b1s[4 * to + o]);
            #pragma unroll
            for (int pp = 0; pp < 8; pp++) acc[o][pp] = bb;
        }
        #pragma unroll
        for (int i = 0; i < EMB; i++) {
            float4 w = *(const float4*)&w1s[i * HID + 4 * to];
            u64 wp0 = pack2(w.x), wp1 = pack2(w.y), wp2 = pack2(w.z), wp3 = pack2(w.w);
            const ulonglong2* av = (const ulonglong2*)&A0[i * RS + 16 * tp];
            ulonglong2 q0 = av[0], q1 = av[1], q2 = av[2], q3 = av[3];
            u64 a[8] = {q0.x, q0.y, q1.x, q1.y, q2.x, q2.y, q3.x, q3.y};
            #pragma unroll
            for (int pp = 0; pp < 8; pp++) {
                acc[0][pp] = fma2(wp0, a[pp], acc[0][pp]);
                acc[1][pp] = fma2(wp1, a[pp], acc[1][pp]);
                acc[2][pp] = fma2(wp2, a[pp], acc[2][pp]);
                acc[3][pp] = fma2(wp3, a[pp], acc[3][pp]);
            }
        }
        #pragma unroll
        for (int o = 0; o < 4; o++) {
            float2* row = (float2*)&A1[(4 * to + o) * RS + 16 * tp];
            #pragma unroll
            for (int pp = 0; pp < 8; pp++) {
                float lo, hi;
                unpack2(acc[o][pp], lo, hi);
                row[pp] = make_float2(fmaxf(lo, 0.0f), fmaxf(hi, 0.0f));
            }
        }
    }
    __syncthreads();

    // ---- phase 2: 64 -> 64 + relu, in-place on A1 (reads fully precede writes) ----
    {
        u64 acc[4][8];
        #pragma unroll
        for (int o = 0; o < 4; o++) {
            u64 bb = pack2(b2s[4 * to + o]);
            #pragma unroll
            for (int pp = 0; pp < 8; pp++) acc[o][pp] = bb;
        }
        #pragma unroll 8
        for (int i = 0; i < HID; i++) {
            float4 w = *(const float4*)&w2s[i * HID + 4 * to];
            u64 wp0 = pack2(w.x), wp1 = pack2(w.y), wp2 = pack2(w.z), wp3 = pack2(w.w);
            const ulonglong2* av = (const ulonglong2*)&A1[i * RS + 16 * tp];
            ulonglong2 q0 = av[0], q1 = av[1], q2 = av[2], q3 = av[3];
            u64 a[8] = {q0.x, q0.y, q1.x, q1.y, q2.x, q2.y, q3.x, q3.y};
            #pragma unroll
            for (int pp = 0; pp < 8; pp++) {
                acc[0][pp] = fma2(wp0, a[pp], acc[0][pp]);
                acc[1][pp] = fma2(wp1, a[pp], acc[1][pp]);
                acc[2][pp] = fma2(wp2, a[pp], acc[2][pp]);
                acc[3][pp] = fma2(wp3, a[pp], acc[3][pp]);
            }
        }
        __syncthreads();   // all reads of A1 complete before overwrite
        #pragma unroll
        for (int o = 0; o < 4; o++) {
            float2* row = (float2*)&A1[(4 * to + o) * RS + 16 * tp];
            #pragma unroll
            for (int pp = 0; pp < 8; pp++) {
                float lo, hi;
                unpack2(acc[o][pp], lo, hi);
                row[pp] = make_float2(fmaxf(lo, 0.0f), fmaxf(hi, 0.0f));
            }
        }
    }
    __syncthreads();

    // ---- phase 3: 64 -> 3, one point per thread ----
    {
        u64 p01 = *(const u64*)&b3s[0];
        u64 p23 = *(const u64*)&b3s[2];
        const u64* w3v = (const u64*)w3s;
        #pragma unroll 8
        for (int i = 0; i < HID; i++) {
            u64 ap = pack2(A1[i * RS + tid]);
            p01 = fma2(ap, w3v[2 * i + 0], p01);
            p23 = fma2(ap, w3v[2 * i + 1], p23);
        }
        float o0, o1, o2, o3;
        unpack2(p01, o0, o1);
        unpack2(p23, o2, o3);
        int idx = base + tid;
        if (idx < n) {
            out[idx * 3 + 0] = o0;
            out[idx * 3 + 1] = o1;
            out[idx * 3 + 2] = o2;
        }
    }
}

extern "C" void kernel_launch(void* const* d_in, const int* in_sizes, int n_in,
                              void* d_out, int out_size) {
    const float* x    = (const float*)d_in[0];
    const float4* e0  = (const float4*)d_in[1];
    const float4* e1  = (const float4*)d_in[2];
    const float4* e2  = (const float4*)d_in[3];
    const float* w1   = (const float*)d_in[4];
    const float* b1   = (const float*)d_in[5];
    const float* w2   = (const float*)d_in[6];
    const float* b2   = (const float*)d_in[7];
    const float* w3   = (const float*)d_in[8];
    const float* b3   = (const float*)d_in[9];
    float* out        = (float*)d_out;
    int n = in_sizes[0] / 3;
    (void)n_in; (void)out_size;
    int blocks = (n + TILE - 1) / TILE;
    densegrid_kernel<<<blocks, THREADS>>>(x, e0, e1, e2, w1, b1, w2, b2, w3, b3, out, n);
}

// round 5
// speedup vs baseline: 1.3140x; 1.1490x over previous
#include <cuda_runtime.h>
#include <cstdint>

// DenseGridNet: trilevel bilinear grid features + MLP 13->64->64->3.
// GEMM tiling: 64 points/CTA, 128 threads (4 warps). Activations staged in
// SMEM; per-thread register tile = 2 outputs x 16 points, point-pairs packed
// as fma.rn.f32x2 (exact fp32, 2x FFMA throughput). 4 warps/CTA at the same
// smem footprint as R4 -> ~2x warps/SMSP to hide LDS/gather latency.

#define HID 64
#define EMB 13
#define TILE 64
#define THREADS 128
#define RS 68   // activation row stride (floats): multiple of 4 for LDS.128

typedef unsigned long long u64;

__device__ __forceinline__ u64 pack2(float a) {
    u64 r;
    asm("mov.b64 %0, {%1, %1};" : "=l"(r) : "f"(a));
    return r;
}
__device__ __forceinline__ u64 fma2(u64 a, u64 b, u64 c) {
    u64 d;
    asm("fma.rn.f32x2 %0, %1, %2, %3;" : "=l"(d) : "l"(a), "l"(b), "l"(c));
    return d;
}
__device__ __forceinline__ void unpack2(u64 p, float& lo, float& hi) {
    asm("mov.b64 {%0, %1}, %2;" : "=f"(lo), "=f"(hi) : "l"(p));
}

__device__ __forceinline__ float4 bilerp_level(const float4* __restrict__ tab,
                                               int res, float u, float v) {
    float sx = u * (float)res;
    float sy = v * (float)res;
    int x0 = (int)sx;            // truncation; matches astype(int32) for non-neg
    int y0 = (int)sy;
    float wx = sx - (float)x0;
    float wy = sy - (float)y0;
    int x1 = min(x0 + 1, res);
    int y1 = min(y0 + 1, res);
    // Reference indexes with row stride == res (not res+1). Replicate exactly.
    int r0 = y0 * res;
    int r1 = y1 * res;
    float4 v00 = tab[r0 + x0];
    float4 v10 = tab[r0 + x1];
    float4 v01 = tab[r1 + x0];
    float4 v11 = tab[r1 + x1];
    float omwx = 1.0f - wx;
    float omwy = 1.0f - wy;
    float4 o;
    float t, c;
    t = v00.x * omwx + v10.x * wx; c = v01.x * omwx + v11.x * wx; o.x = t * omwy + c * wy;
    t = v00.y * omwx + v10.y * wx; c = v01.y * omwx + v11.y * wx; o.y = t * omwy + c * wy;
    t = v00.z * omwx + v10.z * wx; c = v01.z * omwx + v11.z * wx; o.z = t * omwy + c * wy;
    t = v00.w * omwx + v10.w * wx; c = v01.w * omwx + v11.w * wx; o.w = t * omwy + c * wy;
    return o;
}

__global__ __launch_bounds__(THREADS)
void densegrid_kernel(const float* __restrict__ x,
                      const float4* __restrict__ emb0,
                      const float4* __restrict__ emb1,
                      const float4* __restrict__ emb2,
                      const float* __restrict__ w1, const float* __restrict__ b1,
                      const float* __restrict__ w2, const float* __restrict__ b2,
                      const float* __restrict__ w3, const float* __restrict__ b3,
                      float* __restrict__ out, int n) {
    __shared__ __align__(16) float w1s[EMB * HID];
    __shared__ __align__(16) float b1s[HID];
    __shared__ __align__(16) float w2s[HID * HID];
    __shared__ __align__(16) float b2s[HID];
    __shared__ __align__(16) float w3s[HID * 4];   // 64x3 padded to 64x4
    __shared__ __align__(16) float b3s[4];
    __shared__ __align__(16) float A0[EMB * RS];   // input features [13][pts]
    __shared__ __align__(16) float A1[HID * RS];   // activations    [64][pts]

    const int tid = threadIdx.x;

    // ---- cooperative weight staging ----
    for (int t = tid; t < EMB * HID; t += THREADS) w1s[t] = w1[t];
    for (int t = tid; t < HID; t += THREADS) b1s[t] = b1[t];
    for (int t = tid; t < HID * HID; t += THREADS) w2s[t] = w2[t];
    for (int t = tid; t < HID; t += THREADS) b2s[t] = b2[t];
    for (int t = tid; t < HID * 4; t += THREADS) {
        int r = t >> 2, c = t & 3;
        w3s[t] = (c < 3) ? w3[r * 3 + c] : 0.0f;
    }
    if (tid < 4) b3s[tid] = (tid < 3) ? b3[tid] : 0.0f;

    const int base = blockIdx.x * TILE;

    // ---- phase 0: features. Warps 0-1: idf + level0 for point tid.
    //      Warps 2-3: level1 + level2 for point tid-64. No divergence. ----
    {
        int p = tid & 63;
        int idx = base + p;
        if (idx >= n) idx = n - 1;
        float u = x[idx * 3 + 1];
        float v = x[idx * 3 + 2];
        if (tid < 64) {
            float idf = x[idx * 3 + 0];
            float4 f0 = bilerp_level(emb0, 512, u, v);
            A0[0 * RS + p] = idf;
            A0[1 * RS + p] = f0.x; A0[2 * RS + p] = f0.y;
            A0[3 * RS + p] = f0.z; A0[4 * RS + p] = f0.w;
        } else {
            float4 f1 = bilerp_level(emb1, 264, u, v);
            float4 f2 = bilerp_level(emb2, 16,  u, v);
            A0[5 * RS + p]  = f1.x; A0[6 * RS + p]  = f1.y;
            A0[7 * RS + p]  = f1.z; A0[8 * RS + p]  = f1.w;
            A0[9 * RS + p]  = f2.x; A0[10 * RS + p] = f2.y;
            A0[11 * RS + p] = f2.z; A0[12 * RS + p] = f2.w;
        }
    }
    __syncthreads();

    const int to = tid & 31;   // output pair id: outs [2*to, 2*to+1]
    const int tp = tid >> 5;   // point group: pts [16*tp, 16*tp+15] (const per warp)

    // ---- phase 1: 13 -> 64 + relu, into A1 ----
    {
        u64 acc[2][8];
        #pragma unroll
        for (int o = 0; o < 2; o++) {
            u64 bb = pack2(b1s[2 * to + o]);
            #pragma unroll
            for (int pp = 0; pp < 8; pp++) acc[o][pp] = bb;
        }
        #pragma unroll
        for (int i = 0; i < EMB; i++) {
            float2 w = *(const float2*)&w1s[i * HID + 2 * to];
            u64 wp0 = pack2(w.x), wp1 = pack2(w.y);
            const ulonglong2* av = (const ulonglong2*)&A0[i * RS + 16 * tp];
            ulonglong2 q0 = av[0], q1 = av[1], q2 = av[2], q3 = av[3];
            u64 a[8] = {q0.x, q0.y, q1.x, q1.y, q2.x, q2.y, q3.x, q3.y};
            #pragma unroll
            for (int pp = 0; pp < 8; pp++) {
                acc[0][pp] = fma2(wp0, a[pp], acc[0][pp]);
                acc[1][pp] = fma2(wp1, a[pp], acc[1][pp]);
            }
        }
        #pragma unroll
        for (int o = 0; o < 2; o++) {
            float2* row = (float2*)&A1[(2 * to + o) * RS + 16 * tp];
            #pragma unroll
            for (int pp = 0; pp < 8; pp++) {
                float lo, hi;
                unpack2(acc[o][pp], lo, hi);
                row[pp] = make_float2(fmaxf(lo, 0.0f), fmaxf(hi, 0.0f));
            }
        }
    }
    __syncthreads();

    // ---- phase 2: 64 -> 64 + relu, in-place on A1 ----
    {
        u64 acc[2][8];
        #pragma unroll
        for (int o = 0; o < 2; o++) {
            u64 bb = pack2(b2s[2 * to + o]);
            #pragma unroll
            for (int pp = 0; pp < 8; pp++) acc[o][pp] = bb;
        }
        #pragma unroll 8
        for (int i = 0; i < HID; i++) {
            float2 w = *(const float2*)&w2s[i * HID + 2 * to];
            u64 wp0 = pack2(w.x), wp1 = pack2(w.y);
            const ulonglong2* av = (const ulonglong2*)&A1[i * RS + 16 * tp];
            ulonglong2 q0 = av[0], q1 = av[1], q2 = av[2], q3 = av[3];
            u64 a[8] = {q0.x, q0.y, q1.x, q1.y, q2.x, q2.y, q3.x, q3.y};
            #pragma unroll
            for (int pp = 0; pp < 8; pp++) {
                acc[0][pp] = fma2(wp0, a[pp], acc[0][pp]);
                acc[1][pp] = fma2(wp1, a[pp], acc[1][pp]);
            }
        }
        __syncthreads();   // all reads of A1 complete before overwrite
        #pragma unroll
        for (int o = 0; o < 2; o++) {
            float2* row = (float2*)&A1[(2 * to + o) * RS + 16 * tp];
            #pragma unroll
            for (int pp = 0; pp < 8; pp++) {
                float lo, hi;
                unpack2(acc[o][pp], lo, hi);
                row[pp] = make_float2(fmaxf(lo, 0.0f), fmaxf(hi, 0.0f));
            }
        }
    }
    __syncthreads();

    // ---- phase 3: 64 -> 3, one point per thread (warps 0-1) ----
    if (tid < TILE) {
        u64 p01 = *(const u64*)&b3s[0];
        u64 p23 = *(const u64*)&b3s[2];
        const u64* w3v = (const u64*)w3s;
        #pragma unroll 8
        for (int i = 0; i < HID; i++) {
            u64 ap = pack2(A1[i * RS + tid]);
            p01 = fma2(ap, w3v[2 * i + 0], p01);
            p23 = fma2(ap, w3v[2 * i + 1], p23);
        }
        float o0, o1, o2, o3;
        unpack2(p01, o0, o1);
        unpack2(p23, o2, o3);
        int idx = base + tid;
        if (idx < n) {
            out[idx * 3 + 0] = o0;
            out[idx * 3 + 1] = o1;
            out[idx * 3 + 2] = o2;
        }
    }
}

extern "C" void kernel_launch(void* const* d_in, const int* in_sizes, int n_in,
                              void* d_out, int out_size) {
    const float* x    = (const float*)d_in[0];
    const float4* e0  = (const float4*)d_in[1];
    const float4* e1  = (const float4*)d_in[2];
    const float4* e2  = (const float4*)d_in[3];
    const float* w1   = (const float*)d_in[4];
    const float* b1   = (const float*)d_in[5];
    const float* w2   = (const float*)d_in[6];
    const float* b2   = (const float*)d_in[7];
    const float* w3   = (const float*)d_in[8];
    const float* b3   = (const float*)d_in[9];
    float* out        = (float*)d_out;
    int n = in_sizes[0] / 3;
    (void)n_in; (void)out_size;
    int blocks = (n + TILE - 1) / TILE;
    densegrid_kernel<<<blocks, THREADS>>>(x, e0, e1, e2, w1, b1, w2, b2, w3, b3, out, n);
}